// round 15
// baseline (speedup 1.0000x reference)
#include <cuda_runtime.h>

// TokenMixer: out = x_pos * (1 - sigmoid( <x_pre,x_pos> / (||x_pre||*||x_pos||) ))
// Shapes: [N=4096, B=16, C=512] f32. One warp per row.
//
// R15 (== R13 exact, confirmation run): 1024 threads/block (32 warps),
// 2048 blocks. R13 scored 61.54us harness — 0.4us below the tight
// 61.95-62.21 cluster of every 256/512-thr run, and identical binaries
// reproduce harness timing to +/-0.1us (R12==R14, R8==R9==R11), so this
// is likely real: fewer CTA dispatches per graph replay. Single-shot ncu
// captures have +/-2.5us clock-state variance (R12 vs R14, same binary)
// and are NOT decision-bearing.
//
// Per-warp code (fixed since R7): 256-bit v8 global ld/st, x_pos
// register-resident (each byte read exactly once), 3-scalar warp tree
// reduce, MUFU.RSQ tail (1/max(sqrt(s),eps) == min(rsqrt(s),1e12)),
// 1 - sigmoid(d) == 1/(1+exp(d)).

#define ROWS_TOTAL (4096 * 16)
#define FLOATS_PER_ROW 512
#define WARPS_PER_BLOCK 32

__device__ __forceinline__ void ldg256(const float* __restrict__ p, float r[8]) {
    asm("ld.global.v8.f32 {%0,%1,%2,%3,%4,%5,%6,%7}, [%8];"
        : "=f"(r[0]), "=f"(r[1]), "=f"(r[2]), "=f"(r[3]),
          "=f"(r[4]), "=f"(r[5]), "=f"(r[6]), "=f"(r[7])
        : "l"(p));
}

__device__ __forceinline__ void stg256(float* __restrict__ p, const float r[8]) {
    asm volatile("st.global.v8.f32 [%0], {%1,%2,%3,%4,%5,%6,%7,%8};"
        :: "l"(p),
           "f"(r[0]), "f"(r[1]), "f"(r[2]), "f"(r[3]),
           "f"(r[4]), "f"(r[5]), "f"(r[6]), "f"(r[7])
        : "memory");
}

__global__ __launch_bounds__(WARPS_PER_BLOCK * 32)
void token_mixer_kernel(const float* __restrict__ pre,
                        const float* __restrict__ pos,
                        float* __restrict__ out) {
    const int warp_id = threadIdx.x >> 5;
    const int lane    = threadIdx.x & 31;
    const int row     = blockIdx.x * WARPS_PER_BLOCK + warp_id;  // exact: 2048*32 == ROWS_TOTAL

    const size_t base = (size_t)row * FLOATS_PER_ROW + lane * 8;
    const float* __restrict__ p = pre + base;
    const float* __restrict__ q = pos + base;

    // Front-batch: 4 x 256-bit loads (2 per input). Warp covers 1KB per op.
    float a0[8], a1[8], b0[8], b1[8];
    ldg256(p,       a0);
    ldg256(q,       b0);
    ldg256(p + 256, a1);
    ldg256(q + 256, b1);

    float dot = 0.f, sa = 0.f, sb = 0.f;
    #pragma unroll
    for (int i = 0; i < 8; i++) {
        dot += a0[i] * b0[i];
        sa  += a0[i] * a0[i];
        sb  += b0[i] * b0[i];
        dot += a1[i] * b1[i];
        sa  += a1[i] * a1[i];
        sb  += b1[i] * b1[i];
    }

    // Warp tree-reduce the three scalars (interleaved chains).
    #pragma unroll
    for (int off = 16; off > 0; off >>= 1) {
        dot += __shfl_xor_sync(0xffffffffu, dot, off);
        sa  += __shfl_xor_sync(0xffffffffu, sa,  off);
        sb  += __shfl_xor_sync(0xffffffffu, sb,  off);
    }

    // 1/max(sqrt(s), 1e-12) == min(rsqrt(s), 1e12): two MUFU.RSQ, no div.
    const float ra = fminf(rsqrtf(sa), 1e12f);
    const float rb = fminf(rsqrtf(sb), 1e12f);
    const float d  = dot * ra * rb;
    // 1 - sigmoid(d) = 1 / (1 + exp(d))
    const float w  = 1.0f / (1.0f + __expf(d));

    #pragma unroll
    for (int i = 0; i < 8; i++) { b0[i] *= w; b1[i] *= w; }

    float* __restrict__ o = out + base;
    stg256(o,       b0);
    stg256(o + 256, b1);
}

extern "C" void kernel_launch(void* const* d_in, const int* in_sizes, int n_in,
                              void* d_out, int out_size) {
    const float* pre = (const float*)d_in[0];
    const float* pos = (const float*)d_in[1];
    float* out = (float*)d_out;
    const int blocks = ROWS_TOTAL / WARPS_PER_BLOCK;  // 2048
    token_mixer_kernel<<<blocks, WARPS_PER_BLOCK * 32>>>(pre, pos, out);
}

// round 16
// speedup vs baseline: 1.0057x; 1.0057x over previous
#include <cuda_runtime.h>

// TokenMixer: out = x_pos * (1 - sigmoid( <x_pre,x_pos> / (||x_pre||*||x_pos||) ))
// Shapes: [N=4096, B=16, C=512] f32. One warp per row.
//
// FINAL (== R12, best clean profile: ncu 51.71us, 6778 GB/s = 85.6% DRAM):
//   - 512 threads/block (16 warps), 4096 blocks. Granularity sweep,
//     clean-capture ncu: 256thr 52.7-53.3us (n=5), 512thr 51.7us,
//     1024thr 54.2-54.4us (n=2; 46 regs -> 1 CTA/SM, whole-SM wave
//     quantization). 512 is the reproduced optimum.
//   - 256-bit v8 global ld/st (4 loads + 2 stores per lane).
//   - x_pos register-resident: each byte read exactly once.
//   - 3-scalar warp tree reduce (interleaved shfl chains).
//   - MUFU.RSQ tail: 1/max(sqrt(s),eps) == min(rsqrt(s),1e12).
//   - 1 - sigmoid(d) == 1/(1+exp(d)).
//
// Roofline: 384 MB mandatory 2:1 read:write stream at ~85% of 8TB/s HBM
// spec. Non-binding: occupancy 38-82%, MLP/warp 8-16, L1 bypass, minBlocks.
// Regressions: L2 evict-first (.cs), cross-row prefetch/persistence,
// 1024-thr blocks. Measurement notes: harness dur_us noise +/-0.4us;
// single-shot ncu occasionally anomalous (R14) — trust clean profiles.

#define ROWS_TOTAL (4096 * 16)
#define FLOATS_PER_ROW 512
#define WARPS_PER_BLOCK 16

__device__ __forceinline__ void ldg256(const float* __restrict__ p, float r[8]) {
    asm("ld.global.v8.f32 {%0,%1,%2,%3,%4,%5,%6,%7}, [%8];"
        : "=f"(r[0]), "=f"(r[1]), "=f"(r[2]), "=f"(r[3]),
          "=f"(r[4]), "=f"(r[5]), "=f"(r[6]), "=f"(r[7])
        : "l"(p));
}

__device__ __forceinline__ void stg256(float* __restrict__ p, const float r[8]) {
    asm volatile("st.global.v8.f32 [%0], {%1,%2,%3,%4,%5,%6,%7,%8};"
        :: "l"(p),
           "f"(r[0]), "f"(r[1]), "f"(r[2]), "f"(r[3]),
           "f"(r[4]), "f"(r[5]), "f"(r[6]), "f"(r[7])
        : "memory");
}

__global__ __launch_bounds__(WARPS_PER_BLOCK * 32)
void token_mixer_kernel(const float* __restrict__ pre,
                        const float* __restrict__ pos,
                        float* __restrict__ out) {
    const int warp_id = threadIdx.x >> 5;
    const int lane    = threadIdx.x & 31;
    const int row     = blockIdx.x * WARPS_PER_BLOCK + warp_id;  // exact: 4096*16 == ROWS_TOTAL

    const size_t base = (size_t)row * FLOATS_PER_ROW + lane * 8;
    const float* __restrict__ p = pre + base;
    const float* __restrict__ q = pos + base;

    // Front-batch: 4 x 256-bit loads (2 per input). Warp covers 1KB per op.
    float a0[8], a1[8], b0[8], b1[8];
    ldg256(p,       a0);
    ldg256(q,       b0);
    ldg256(p + 256, a1);
    ldg256(q + 256, b1);

    float dot = 0.f, sa = 0.f, sb = 0.f;
    #pragma unroll
    for (int i = 0; i < 8; i++) {
        dot += a0[i] * b0[i];
        sa  += a0[i] * a0[i];
        sb  += b0[i] * b0[i];
        dot += a1[i] * b1[i];
        sa  += a1[i] * a1[i];
        sb  += b1[i] * b1[i];
    }

    // Warp tree-reduce the three scalars (interleaved chains).
    #pragma unroll
    for (int off = 16; off > 0; off >>= 1) {
        dot += __shfl_xor_sync(0xffffffffu, dot, off);
        sa  += __shfl_xor_sync(0xffffffffu, sa,  off);
        sb  += __shfl_xor_sync(0xffffffffu, sb,  off);
    }

    // 1/max(sqrt(s), 1e-12) == min(rsqrt(s), 1e12): two MUFU.RSQ, no div.
    const float ra = fminf(rsqrtf(sa), 1e12f);
    const float rb = fminf(rsqrtf(sb), 1e12f);
    const float d  = dot * ra * rb;
    // 1 - sigmoid(d) = 1 / (1 + exp(d))
    const float w  = 1.0f / (1.0f + __expf(d));

    #pragma unroll
    for (int i = 0; i < 8; i++) { b0[i] *= w; b1[i] *= w; }

    float* __restrict__ o = out + base;
    stg256(o,       b0);
    stg256(o + 256, b1);
}

extern "C" void kernel_launch(void* const* d_in, const int* in_sizes, int n_in,
                              void* d_out, int out_size) {
    const float* pre = (const float*)d_in[0];
    const float* pos = (const float*)d_in[1];
    float* out = (float*)d_out;
    const int blocks = ROWS_TOTAL / WARPS_PER_BLOCK;  // 4096
    token_mixer_kernel<<<blocks, WARPS_PER_BLOCK * 32>>>(pre, pos, out);
}